// round 5
// baseline (speedup 1.0000x reference)
#include <cuda_runtime.h>
#include <cuda_fp16.h>
#include <cuda.h>
#include <cstdint>

// Problem dims (fixed by the dataset)
constexpr int TT = 4096;    // tokens
constexpr int KK = 4096;    // in_features
constexpr int II = 11008;   // intermediate
constexpr int OO = 4096;    // out_features

constexpr int NS = 4;                    // pipeline stages
constexpr uint32_t GU_STAGE = 49152;     // A 32K | Bg 8K | Bu 8K
constexpr uint32_t DN_STAGE = 32768;     // A 16K | B0 8K | B1 8K
constexpr int GU_SMEM = 1024 + NS * (int)GU_STAGE;  // 197632
constexpr int DN_SMEM = 1024 + NS * (int)DN_STAGE;  // 132096

// ---------------- device scratch ----------------
__device__ __align__(256) __half g_Wg[(size_t)KK * II];
__device__ __align__(256) __half g_Wu[(size_t)KK * II];
__device__ __align__(256) __half g_Wd[(size_t)II * OO];
__device__ __align__(256) __half g_X [(size_t)TT * KK];
__device__ __align__(256) __half g_H [(size_t)TT * II];

// ---------------- PTX helpers ----------------
__device__ __forceinline__ uint32_t smem_u32(const void* p) {
    return (uint32_t)__cvta_generic_to_shared(p);
}

#define MBAR_INIT(addr, cnt) \
    asm volatile("mbarrier.init.shared.b64 [%0], %1;" :: "r"(addr), "r"(cnt) : "memory")

#define MBAR_EXPECT_TX(addr, bytes) \
    asm volatile("mbarrier.arrive.expect_tx.shared.b64 _, [%0], %1;" :: "r"(addr), "r"(bytes) : "memory")

#define MBAR_ARRIVE(addr) \
    asm volatile("mbarrier.arrive.shared.b64 _, [%0];" :: "r"(addr) : "memory")

#define MBAR_WAIT(addr, par) do {                                                       \
    uint32_t _m = (addr); uint32_t _p = (par); uint32_t _d;                             \
    asm volatile("{\n .reg .pred p;\n"                                                  \
        " mbarrier.try_wait.parity.acquire.cta.shared::cta.b64 p, [%1], %2;\n"          \
        " selp.b32 %0, 1, 0, p;\n}"                                                     \
        : "=r"(_d) : "r"(_m), "r"(_p) : "memory");                                      \
    if (!_d) {                                                                          \
        asm volatile("{\n .reg .pred P1;\n"                                             \
            "WL_%=:\n"                                                                  \
            " mbarrier.try_wait.parity.acquire.cta.shared::cta.b64 P1, [%0], %1, 0x989680;\n" \
            " @P1 bra.uni WD_%=;\n bra.uni WL_%=;\nWD_%=:\n}"                           \
            :: "r"(_m), "r"(_p) : "memory");                                            \
    }                                                                                   \
} while (0)

#define MBAR_WAIT_RLX(addr, par) do {                                                   \
    uint32_t _m = (addr); uint32_t _p = (par); uint32_t _d;                             \
    asm volatile("{\n .reg .pred p;\n"                                                  \
        " mbarrier.try_wait.parity.relaxed.cta.shared::cta.b64 p, [%1], %2, 0x989680;\n"\
        " selp.b32 %0, 1, 0, p;\n}"                                                     \
        : "=r"(_d) : "r"(_m), "r"(_p) : "memory");                                      \
    if (!_d) {                                                                          \
        asm volatile("{\n .reg .pred P1;\n"                                             \
            "WL_%=:\n"                                                                  \
            " mbarrier.try_wait.parity.relaxed.cta.shared::cta.b64 P1, [%0], %1, 0x989680;\n" \
            " @P1 bra.uni WD_%=;\n bra.uni WL_%=;\nWD_%=:\n}"                           \
            :: "r"(_m), "r"(_p) : "memory");                                            \
    }                                                                                   \
} while (0)

#define TMA2D(dst, map, c0, c1, bar) \
    asm volatile("cp.async.bulk.tensor.2d.shared::cta.global.tile.mbarrier::complete_tx::bytes " \
                 "[%0], [%1, {%2, %3}], [%4];" \
                 :: "r"(dst), "l"(map), "r"(c0), "r"(c1), "r"(bar) : "memory")

#define LDSM4(r, addr) \
    asm volatile("ldmatrix.sync.aligned.m8n8.x4.shared.b16 {%0,%1,%2,%3}, [%4];\n" \
        : "=r"((r)[0]), "=r"((r)[1]), "=r"((r)[2]), "=r"((r)[3]) : "r"(addr))

#define LDSM4T(r0, r1, r2, r3, addr) \
    asm volatile("ldmatrix.sync.aligned.m8n8.x4.trans.shared.b16 {%0,%1,%2,%3}, [%4];\n" \
        : "=r"(r0), "=r"(r1), "=r"(r2), "=r"(r3) : "r"(addr))

#define MMA16816(d, a, b) \
    asm volatile("mma.sync.aligned.m16n8k16.row.col.f32.f16.f16.f32 " \
        "{%0,%1,%2,%3}, {%4,%5,%6,%7}, {%8,%9}, {%0,%1,%2,%3};\n" \
        : "+f"((d)[0]), "+f"((d)[1]), "+f"((d)[2]), "+f"((d)[3]) \
        : "r"((a)[0]), "r"((a)[1]), "r"((a)[2]), "r"((a)[3]), "r"((b)[0]), "r"((b)[1]))

// ---------------- x fp32 -> fp16 ----------------
__global__ void f2h_kernel(const float* __restrict__ x) {
    size_t i = (size_t)blockIdx.x * blockDim.x + threadIdx.x;
    float4 v = ((const float4*)x)[i];
    __half2* o = (__half2*)g_X;
    o[2 * i + 0] = __floats2half2_rn(v.x, v.y);
    o[2 * i + 1] = __floats2half2_rn(v.z, v.w);
}

// ---------------- AWQ int4 dequant -> fp16 row-major [rows, cols] ----------------
template <int WHICH>
__global__ void dequant_kernel(const int* __restrict__ qw, const float* __restrict__ sc,
                               const int* __restrict__ qz, int rows, int cols) {
    __half* W = (WHICH == 0) ? g_Wg : (WHICH == 1) ? g_Wu : g_Wd;
    const int wpr = cols >> 3;
    size_t idx = (size_t)blockIdx.x * blockDim.x + threadIdx.x;
    if (idx >= (size_t)rows * wpr) return;
    int j = (int)(idx % wpr);
    int k = (int)(idx / wpr);
    int grp = k >> 7;

    unsigned w = ((const unsigned*)qw)[idx];
    unsigned z = ((const unsigned*)qz)[(size_t)grp * wpr + j];
    const float* srow = sc + (size_t)grp * cols + j * 8;
    float4 s0 = *(const float4*)(srow);
    float4 s1 = *(const float4*)(srow + 4);

    __half2 h[4];
    h[0] = __floats2half2_rn((float)((int)(w & 0xF)         - (int)(z & 0xF))         * s0.x,
                             (float)((int)((w >> 4) & 0xF)  - (int)((z >> 4) & 0xF))  * s0.y);
    h[1] = __floats2half2_rn((float)((int)((w >> 8) & 0xF)  - (int)((z >> 8) & 0xF))  * s0.z,
                             (float)((int)((w >> 12) & 0xF) - (int)((z >> 12) & 0xF)) * s0.w);
    h[2] = __floats2half2_rn((float)((int)((w >> 16) & 0xF) - (int)((z >> 16) & 0xF)) * s1.x,
                             (float)((int)((w >> 20) & 0xF) - (int)((z >> 20) & 0xF)) * s1.y);
    h[3] = __floats2half2_rn((float)((int)((w >> 24) & 0xF) - (int)((z >> 24) & 0xF)) * s1.z,
                             (float)((int)((w >> 28) & 0xF) - (int)((z >> 28) & 0xF)) * s1.w);

    *(uint4*)(W + (size_t)k * cols + j * 8) = *(uint4*)h;
}

// ============================================================================
// GEMM1 (fused gate+up): BM=256, 64 gate cols + 64 up cols, BK=64 per stage.
// 512 threads = 16 warps = 4(m) x 4(n). Warp: 64 rows x (16 gate + 16 up) cols.
// ============================================================================
constexpr int GU_KT = KK / 64;   // 64

__global__ __launch_bounds__(512, 1) void gemm_gateup(
    const __grid_constant__ CUtensorMap mA,
    const __grid_constant__ CUtensorMap mBg,
    const __grid_constant__ CUtensorMap mBu)
{
    extern __shared__ __align__(1024) char smem[];
    const uint32_t sb = smem_u32(smem);
    const int tid  = threadIdx.x;
    const int lane = tid & 31;
    const int warp = tid >> 5;
    const int wm   = warp & 3;
    const int wn   = warp >> 2;
    const int m0   = blockIdx.x * 256;
    const int n0   = blockIdx.y * 64;

    if (tid == 0) {
        for (int i = 0; i < NS; ++i) {
            MBAR_INIT(sb + i * 16, 1);       // full (tx-based)
            MBAR_INIT(sb + i * 16 + 8, 16);  // empty (one arrive per warp)
        }
    }
    __syncthreads();

#define GU_LOAD(slot, stg) do {                                     \
        uint32_t _d  = sb + 1024 + (uint32_t)(slot) * GU_STAGE;     \
        uint32_t _fb = sb + (slot) * 16;                            \
        int _k0 = (stg) * 64;                                       \
        MBAR_EXPECT_TX(_fb, GU_STAGE);                              \
        TMA2D(_d,         &mA,  _k0, m0, _fb);                      \
        TMA2D(_d + 32768, &mBg, n0,  _k0, _fb);                     \
        TMA2D(_d + 40960, &mBu, n0,  _k0, _fb);                     \
    } while (0)

    if (tid == 0) {
#pragma unroll
        for (int p = 0; p < NS; ++p) GU_LOAD(p, p);
    }

    float cg[4][2][4];
    float cu[4][2][4];
#pragma unroll
    for (int i = 0; i < 4; i++)
#pragma unroll
        for (int j = 0; j < 2; j++)
#pragma unroll
            for (int l = 0; l < 4; l++) { cg[i][j][l] = 0.f; cu[i][j][l] = 0.f; }

    const uint32_t xr = (uint32_t)(lane & 7) << 4;
    const uint32_t aro = (uint32_t)(wm * 64 + (lane & 15)) * 128;
    const uint32_t acb = (uint32_t)((lane >> 4) << 4);
    const uint32_t bro = (uint32_t)(lane & 15) * 128;
    const uint32_t bcb = (uint32_t)(wn * 32 + ((lane >> 4) << 4));

    for (int s = 0; s < GU_KT; ++s) {
        const int slot = s & (NS - 1);
        const uint32_t par = (uint32_t)((s / NS) & 1);
        MBAR_WAIT(sb + slot * 16, par);

        const uint32_t abase  = sb + 1024 + (uint32_t)slot * GU_STAGE;
        const uint32_t bgbase = abase + 32768;
        const uint32_t bubase = abase + 40960;

#pragma unroll
        for (int ks = 0; ks < 4; ++ks) {
            uint32_t a[4][4];
#pragma unroll
            for (int mi = 0; mi < 4; ++mi) {
                uint32_t addr = abase + aro + (uint32_t)(mi * 16 * 128) +
                                (((uint32_t)(ks * 32) + acb) ^ xr);
                LDSM4(a[mi], addr);
            }
            uint32_t bg[2][2], bu[2][2];
            {
                uint32_t off = bro + (uint32_t)(ks * 16 * 128) + (bcb ^ xr);
                LDSM4T(bg[0][0], bg[0][1], bg[1][0], bg[1][1], bgbase + off);
                LDSM4T(bu[0][0], bu[0][1], bu[1][0], bu[1][1], bubase + off);
            }
            // all smem reads for this stage are issued -> release the buffer
            if (ks == 3 && lane == 0) MBAR_ARRIVE(sb + slot * 16 + 8);
#pragma unroll
            for (int mi = 0; mi < 4; ++mi)
#pragma unroll
                for (int nj = 0; nj < 2; ++nj) {
                    MMA16816(cg[mi][nj], a[mi], bg[nj]);
                    MMA16816(cu[mi][nj], a[mi], bu[nj]);
                }
        }

        if (tid == 0 && s + NS < GU_KT) {
            MBAR_WAIT_RLX(sb + slot * 16 + 8, par);
            GU_LOAD(slot, s + NS);
        }
    }
#undef GU_LOAD

    // epilogue: h = silu(g) * u (warp-local)
#pragma unroll
    for (int mi = 0; mi < 4; ++mi)
#pragma unroll
        for (int nj = 0; nj < 2; ++nj) {
            int r = m0 + wm * 64 + mi * 16 + (lane >> 2);
            int c = n0 + wn * 16 + nj * 8 + (lane & 3) * 2;
            float g0 = cg[mi][nj][0], g1 = cg[mi][nj][1];
            float g2 = cg[mi][nj][2], g3 = cg[mi][nj][3];
            float u0 = cu[mi][nj][0], u1 = cu[mi][nj][1];
            float u2 = cu[mi][nj][2], u3 = cu[mi][nj][3];
            float h0 = g0 / (1.f + __expf(-g0)) * u0;
            float h1 = g1 / (1.f + __expf(-g1)) * u1;
            float h2 = g2 / (1.f + __expf(-g2)) * u2;
            float h3 = g3 / (1.f + __expf(-g3)) * u3;
            *(__half2*)(g_H + (size_t)r * II + c)       = __floats2half2_rn(h0, h1);
            *(__half2*)(g_H + (size_t)(r + 8) * II + c) = __floats2half2_rn(h2, h3);
        }
}

// ============================================================================
// GEMM2 (down): BM=128, BN=128 (two 64-col B tiles), BK=64 per stage.
// 512 threads = 16 warps = 2(m) x 8(n). Warp tile: 64 x 16.
// Grid (32, 32) = 1024 CTAs -> 6.92 waves (vs 3.46 before): tail loss 15% -> 1%.
// ============================================================================
constexpr int DN_KT = II / 64;   // 172

__global__ __launch_bounds__(512, 1) void gemm_down(
    const __grid_constant__ CUtensorMap mA,
    const __grid_constant__ CUtensorMap mB,
    float* __restrict__ out)
{
    extern __shared__ __align__(1024) char smem[];
    const uint32_t sb = smem_u32(smem);
    const int tid  = threadIdx.x;
    const int lane = tid & 31;
    const int warp = tid >> 5;
    const int wm   = warp & 1;   // 2 warps along M (64 rows each)
    const int wn   = warp >> 1;  // 8 warps along N (16 cols each)
    const int m0   = blockIdx.x * 128;
    const int n0   = blockIdx.y * 128;

    if (tid == 0) {
        for (int i = 0; i < NS; ++i) {
            MBAR_INIT(sb + i * 16, 1);
            MBAR_INIT(sb + i * 16 + 8, 16);
        }
    }
    __syncthreads();

#define DN_LOAD(slot, stg) do {                                     \
        uint32_t _d  = sb + 1024 + (uint32_t)(slot) * DN_STAGE;     \
        uint32_t _fb = sb + (slot) * 16;                            \
        int _k0 = (stg) * 64;                                       \
        MBAR_EXPECT_TX(_fb, DN_STAGE);                              \
        TMA2D(_d,         &mA, _k0, m0,  _fb);                      \
        TMA2D(_d + 16384, &mB, n0,      _k0, _fb);                  \
        TMA2D(_d + 24576, &mB, n0 + 64, _k0, _fb);                  \
    } while (0)

    if (tid == 0) {
#pragma unroll
        for (int p = 0; p < NS; ++p) DN_LOAD(p, p);
    }

    float cc[4][2][4];
#pragma unroll
    for (int i = 0; i < 4; i++)
#pragma unroll
        for (int j = 0; j < 2; j++)
#pragma unroll
            for (int l = 0; l < 4; l++) cc[i][j][l] = 0.f;

    const uint32_t xr = (uint32_t)(lane & 7) << 4;
    const uint32_t aro = (uint32_t)(wm * 64 + (lane & 15)) * 128;
    const uint32_t acb = (uint32_t)((lane >> 4) << 4);
    const uint32_t bro = (uint32_t)(lane & 15) * 128;
    const uint32_t btile = (uint32_t)(wn >> 2) * 8192;           // B0 or B1
    const uint32_t bcb = (uint32_t)((wn & 3) * 32 + ((lane >> 4) << 4));

    for (int s = 0; s < DN_KT; ++s) {
        const int slot = s & (NS - 1);
        const uint32_t par = (uint32_t)((s / NS) & 1);
        MBAR_WAIT(sb + slot * 16, par);

        const uint32_t abase = sb + 1024 + (uint32_t)slot * DN_STAGE;
        const uint32_t bbase = abase + 16384 + btile;

#pragma unroll
        for (int ks = 0; ks < 4; ++ks) {
            uint32_t a[4][4];
#pragma unroll
            for (int mi = 0; mi < 4; ++mi) {
                uint32_t addr = abase + aro + (uint32_t)(mi * 16 * 128) +
                                (((uint32_t)(ks * 32) + acb) ^ xr);
                LDSM4(a[mi], addr);
            }
            uint32_t b[2][2];
            {
                uint32_t addr = bbase + bro + (uint32_t)(ks * 16 * 128) + (bcb ^ xr);
                LDSM4T(b[0][0], b[0][1], b[1][0], b[1][1], addr);
            }
            if (ks == 3 && lane == 0) MBAR_ARRIVE(sb + slot * 16 + 8);
#pragma unroll
            for (int mi = 0; mi < 4; ++mi)
#pragma unroll
                for (int nj = 0; nj < 2; ++nj) MMA16816(cc[mi][nj], a[mi], b[nj]);
        }

        if (tid == 0 && s + NS < DN_KT) {
            MBAR_WAIT_RLX(sb + slot * 16 + 8, par);
            DN_LOAD(slot, s + NS);
        }
    }
#undef DN_LOAD

#pragma unroll
    for (int mi = 0; mi < 4; ++mi)
#pragma unroll
        for (int nj = 0; nj < 2; ++nj) {
            int r = m0 + wm * 64 + mi * 16 + (lane >> 2);
            int c = n0 + wn * 16 + nj * 8 + (lane & 3) * 2;
            *(float2*)(out + (size_t)r * OO + c)       = make_float2(cc[mi][nj][0], cc[mi][nj][1]);
            *(float2*)(out + (size_t)(r + 8) * OO + c) = make_float2(cc[mi][nj][2], cc[mi][nj][3]);
        }
}

// ---------------- host: tensormap construction ----------------
typedef CUresult (*PFN_encode)(CUtensorMap*, CUtensorMapDataType, cuuint32_t, void*,
                               const cuuint64_t*, const cuuint64_t*, const cuuint32_t*,
                               const cuuint32_t*, CUtensorMapInterleave, CUtensorMapSwizzle,
                               CUtensorMapL2promotion, CUtensorMapFloatOOBfill);

static void make_map(PFN_encode enc, CUtensorMap* m, void* ptr,
                     unsigned long long d0, unsigned long long d1,
                     unsigned b0, unsigned b1) {
    cuuint64_t dims[2] = {d0, d1};
    cuuint64_t strides[1] = {d0 * 2};  // fp16 bytes
    cuuint32_t box[2] = {b0, b1};
    cuuint32_t es[2] = {1, 1};
    enc(m, CU_TENSOR_MAP_DATA_TYPE_FLOAT16, 2, ptr, dims, strides, box, es,
        CU_TENSOR_MAP_INTERLEAVE_NONE, CU_TENSOR_MAP_SWIZZLE_128B,
        CU_TENSOR_MAP_L2_PROMOTION_L2_128B, CU_TENSOR_MAP_FLOAT_OOB_FILL_NONE);
}

extern "C" void kernel_launch(void* const* d_in, const int* in_sizes, int n_in,
                              void* d_out, int out_size) {
    (void)in_sizes; (void)n_in; (void)out_size;
    const float* x   = (const float*)d_in[0];
    const int*   gqw = (const int*)d_in[1];
    const float* gsc = (const float*)d_in[2];
    const int*   gqz = (const int*)d_in[3];
    const int*   uqw = (const int*)d_in[4];
    const float* usc = (const float*)d_in[5];
    const int*   uqz = (const int*)d_in[6];
    const int*   dqw = (const int*)d_in[7];
    const float* dsc = (const float*)d_in[8];
    const int*   dqz = (const int*)d_in[9];
    float* out = (float*)d_out;

    PFN_encode enc = nullptr;
    cudaDriverEntryPointQueryResult qr;
    cudaGetDriverEntryPointByVersion("cuTensorMapEncodeTiled", (void**)&enc, 12000,
                                     cudaEnableDefault, &qr);
    void *pX, *pWg, *pWu, *pWd, *pH;
    cudaGetSymbolAddress(&pX,  g_X);
    cudaGetSymbolAddress(&pWg, g_Wg);
    cudaGetSymbolAddress(&pWu, g_Wu);
    cudaGetSymbolAddress(&pWd, g_Wd);
    cudaGetSymbolAddress(&pH,  g_H);

    static CUtensorMap mX, mWg, mWu, mWd, mH;
    make_map(enc, &mX,  pX,  KK, TT, 64, 256);  // A1: X [T,K], box 64x256
    make_map(enc, &mWg, pWg, II, KK, 64, 64);   // Bg: Wg [K,I]
    make_map(enc, &mWu, pWu, II, KK, 64, 64);   // Bu
    make_map(enc, &mH,  pH,  II, TT, 64, 128);  // A2: H [T,I], box 64x128
    make_map(enc, &mWd, pWd, OO, II, 64, 64);   // Bd: Wd [I,O]

    // x -> fp16
    f2h_kernel<<<(TT * KK / 4) / 256, 256>>>(x);

    // dequant weights
    int words1 = KK * (II / 8);
    dequant_kernel<0><<<(words1 + 255) / 256, 256>>>(gqw, gsc, gqz, KK, II);
    dequant_kernel<1><<<(words1 + 255) / 256, 256>>>(uqw, usc, uqz, KK, II);
    int words2 = II * (OO / 8);
    dequant_kernel<2><<<(words2 + 255) / 256, 256>>>(dqw, dsc, dqz, II, OO);

    // fused gate/up GEMM + silu*mul (TMA-fed)
    cudaFuncSetAttribute(gemm_gateup, cudaFuncAttributeMaxDynamicSharedMemorySize, GU_SMEM);
    gemm_gateup<<<dim3(TT / 256, II / 64), 512, GU_SMEM>>>(mX, mWg, mWu);

    // down GEMM (TMA-fed)
    cudaFuncSetAttribute(gemm_down, cudaFuncAttributeMaxDynamicSharedMemorySize, DN_SMEM);
    gemm_down<<<dim3(TT / 128, OO / 128), 512, DN_SMEM>>>(mH, mWd, out);
}

// round 6
// speedup vs baseline: 1.0548x; 1.0548x over previous
#include <cuda_runtime.h>
#include <cuda_fp16.h>
#include <cuda.h>
#include <cstdint>

// Problem dims (fixed by the dataset)
constexpr int TT = 4096;    // tokens
constexpr int KK = 4096;    // in_features
constexpr int II = 11008;   // intermediate
constexpr int OO = 4096;    // out_features

constexpr int NS = 4;                    // pipeline stages
constexpr uint32_t GU_STAGE = 49152;     // A 32K | Bg 8K | Bu 8K
constexpr uint32_t DN_STAGE = 49152;     // A 32K | B0 8K | B1 8K
constexpr int SMEM_BYTES = 1024 + NS * 49152;  // 197632

// ---------------- device scratch ----------------
__device__ __align__(256) __half g_Wg[(size_t)KK * II];
__device__ __align__(256) __half g_Wu[(size_t)KK * II];
__device__ __align__(256) __half g_Wd[(size_t)II * OO];
__device__ __align__(256) __half g_X [(size_t)TT * KK];
__device__ __align__(256) __half g_H [(size_t)TT * II];
__device__ __align__(256) float  g_P [(size_t)TT * OO];   // split-K partial

// ---------------- PTX helpers ----------------
__device__ __forceinline__ uint32_t smem_u32(const void* p) {
    return (uint32_t)__cvta_generic_to_shared(p);
}

#define MBAR_INIT(addr, cnt) \
    asm volatile("mbarrier.init.shared.b64 [%0], %1;" :: "r"(addr), "r"(cnt) : "memory")

#define MBAR_EXPECT_TX(addr, bytes) \
    asm volatile("mbarrier.arrive.expect_tx.shared.b64 _, [%0], %1;" :: "r"(addr), "r"(bytes) : "memory")

#define MBAR_ARRIVE(addr) \
    asm volatile("mbarrier.arrive.shared.b64 _, [%0];" :: "r"(addr) : "memory")

#define MBAR_WAIT(addr, par) do {                                                       \
    uint32_t _m = (addr); uint32_t _p = (par); uint32_t _d;                             \
    asm volatile("{\n .reg .pred p;\n"                                                  \
        " mbarrier.try_wait.parity.acquire.cta.shared::cta.b64 p, [%1], %2;\n"          \
        " selp.b32 %0, 1, 0, p;\n}"                                                     \
        : "=r"(_d) : "r"(_m), "r"(_p) : "memory");                                      \
    if (!_d) {                                                                          \
        asm volatile("{\n .reg .pred P1;\n"                                             \
            "WL_%=:\n"                                                                  \
            " mbarrier.try_wait.parity.acquire.cta.shared::cta.b64 P1, [%0], %1, 0x989680;\n" \
            " @P1 bra.uni WD_%=;\n bra.uni WL_%=;\nWD_%=:\n}"                           \
            :: "r"(_m), "r"(_p) : "memory");                                            \
    }                                                                                   \
} while (0)

#define MBAR_WAIT_RLX(addr, par) do {                                                   \
    uint32_t _m = (addr); uint32_t _p = (par); uint32_t _d;                             \
    asm volatile("{\n .reg .pred p;\n"                                                  \
        " mbarrier.try_wait.parity.relaxed.cta.shared::cta.b64 p, [%1], %2, 0x989680;\n"\
        " selp.b32 %0, 1, 0, p;\n}"                                                     \
        : "=r"(_d) : "r"(_m), "r"(_p) : "memory");                                      \
    if (!_d) {                                                                          \
        asm volatile("{\n .reg .pred P1;\n"                                             \
            "WL_%=:\n"                                                                  \
            " mbarrier.try_wait.parity.relaxed.cta.shared::cta.b64 P1, [%0], %1, 0x989680;\n" \
            " @P1 bra.uni WD_%=;\n bra.uni WL_%=;\nWD_%=:\n}"                           \
            :: "r"(_m), "r"(_p) : "memory");                                            \
    }                                                                                   \
} while (0)

#define TMA2D(dst, map, c0, c1, bar) \
    asm volatile("cp.async.bulk.tensor.2d.shared::cta.global.tile.mbarrier::complete_tx::bytes " \
                 "[%0], [%1, {%2, %3}], [%4];" \
                 :: "r"(dst), "l"(map), "r"(c0), "r"(c1), "r"(bar) : "memory")

#define LDSM4(r, addr) \
    asm volatile("ldmatrix.sync.aligned.m8n8.x4.shared.b16 {%0,%1,%2,%3}, [%4];\n" \
        : "=r"((r)[0]), "=r"((r)[1]), "=r"((r)[2]), "=r"((r)[3]) : "r"(addr))

#define LDSM4T(r0, r1, r2, r3, addr) \
    asm volatile("ldmatrix.sync.aligned.m8n8.x4.trans.shared.b16 {%0,%1,%2,%3}, [%4];\n" \
        : "=r"(r0), "=r"(r1), "=r"(r2), "=r"(r3) : "r"(addr))

#define MMA16816(d, a, b) \
    asm volatile("mma.sync.aligned.m16n8k16.row.col.f32.f16.f16.f32 " \
        "{%0,%1,%2,%3}, {%4,%5,%6,%7}, {%8,%9}, {%0,%1,%2,%3};\n" \
        : "+f"((d)[0]), "+f"((d)[1]), "+f"((d)[2]), "+f"((d)[3]) \
        : "r"((a)[0]), "r"((a)[1]), "r"((a)[2]), "r"((a)[3]), "r"((b)[0]), "r"((b)[1]))

// ---------------- x fp32 -> fp16 ----------------
__global__ void f2h_kernel(const float* __restrict__ x) {
    size_t i = (size_t)blockIdx.x * blockDim.x + threadIdx.x;
    float4 v = ((const float4*)x)[i];
    __half2* o = (__half2*)g_X;
    o[2 * i + 0] = __floats2half2_rn(v.x, v.y);
    o[2 * i + 1] = __floats2half2_rn(v.z, v.w);
}

// ---------------- AWQ int4 dequant -> fp16 row-major [rows, cols] ----------------
template <int WHICH>
__global__ void dequant_kernel(const int* __restrict__ qw, const float* __restrict__ sc,
                               const int* __restrict__ qz, int rows, int cols) {
    __half* W = (WHICH == 0) ? g_Wg : (WHICH == 1) ? g_Wu : g_Wd;
    const int wpr = cols >> 3;
    size_t idx = (size_t)blockIdx.x * blockDim.x + threadIdx.x;
    if (idx >= (size_t)rows * wpr) return;
    int j = (int)(idx % wpr);
    int k = (int)(idx / wpr);
    int grp = k >> 7;

    unsigned w = ((const unsigned*)qw)[idx];
    unsigned z = ((const unsigned*)qz)[(size_t)grp * wpr + j];
    const float* srow = sc + (size_t)grp * cols + j * 8;
    float4 s0 = *(const float4*)(srow);
    float4 s1 = *(const float4*)(srow + 4);

    __half2 h[4];
    h[0] = __floats2half2_rn((float)((int)(w & 0xF)         - (int)(z & 0xF))         * s0.x,
                             (float)((int)((w >> 4) & 0xF)  - (int)((z >> 4) & 0xF))  * s0.y);
    h[1] = __floats2half2_rn((float)((int)((w >> 8) & 0xF)  - (int)((z >> 8) & 0xF))  * s0.z,
                             (float)((int)((w >> 12) & 0xF) - (int)((z >> 12) & 0xF)) * s0.w);
    h[2] = __floats2half2_rn((float)((int)((w >> 16) & 0xF) - (int)((z >> 16) & 0xF)) * s1.x,
                             (float)((int)((w >> 20) & 0xF) - (int)((z >> 20) & 0xF)) * s1.y);
    h[3] = __floats2half2_rn((float)((int)((w >> 24) & 0xF) - (int)((z >> 24) & 0xF)) * s1.z,
                             (float)((int)((w >> 28) & 0xF) - (int)((z >> 28) & 0xF)) * s1.w);

    *(uint4*)(W + (size_t)k * cols + j * 8) = *(uint4*)h;
}

// ============================================================================
// GEMM1 (fused gate+up): BM=256, 64 gate cols + 64 up cols, BK=64 per stage.
// 512 threads = 16 warps = 4(m) x 4(n). Warp: 64 rows x (16 gate + 16 up) cols.
// ============================================================================
constexpr int GU_KT = KK / 64;   // 64

__global__ __launch_bounds__(512, 1) void gemm_gateup(
    const __grid_constant__ CUtensorMap mA,
    const __grid_constant__ CUtensorMap mBg,
    const __grid_constant__ CUtensorMap mBu)
{
    extern __shared__ __align__(1024) char smem[];
    const uint32_t sb = smem_u32(smem);
    const int tid  = threadIdx.x;
    const int lane = tid & 31;
    const int warp = tid >> 5;
    const int wm   = warp & 3;
    const int wn   = warp >> 2;
    const int m0   = blockIdx.x * 256;
    const int n0   = blockIdx.y * 64;

    if (tid == 0) {
        for (int i = 0; i < NS; ++i) {
            MBAR_INIT(sb + i * 16, 1);       // full (tx-based)
            MBAR_INIT(sb + i * 16 + 8, 16);  // empty (one arrive per warp)
        }
    }
    __syncthreads();

#define GU_LOAD(slot, stg) do {                                     \
        uint32_t _d  = sb + 1024 + (uint32_t)(slot) * GU_STAGE;     \
        uint32_t _fb = sb + (slot) * 16;                            \
        int _k0 = (stg) * 64;                                       \
        MBAR_EXPECT_TX(_fb, GU_STAGE);                              \
        TMA2D(_d,         &mA,  _k0, m0, _fb);                      \
        TMA2D(_d + 32768, &mBg, n0,  _k0, _fb);                     \
        TMA2D(_d + 40960, &mBu, n0,  _k0, _fb);                     \
    } while (0)

    if (tid == 0) {
#pragma unroll
        for (int p = 0; p < NS; ++p) GU_LOAD(p, p);
    }

    float cg[4][2][4];
    float cu[4][2][4];
#pragma unroll
    for (int i = 0; i < 4; i++)
#pragma unroll
        for (int j = 0; j < 2; j++)
#pragma unroll
            for (int l = 0; l < 4; l++) { cg[i][j][l] = 0.f; cu[i][j][l] = 0.f; }

    const uint32_t xr = (uint32_t)(lane & 7) << 4;
    const uint32_t aro = (uint32_t)(wm * 64 + (lane & 15)) * 128;
    const uint32_t acb = (uint32_t)((lane >> 4) << 4);
    const uint32_t bro = (uint32_t)(lane & 15) * 128;
    const uint32_t bcb = (uint32_t)(wn * 32 + ((lane >> 4) << 4));

    for (int s = 0; s < GU_KT; ++s) {
        const int slot = s & (NS - 1);
        const uint32_t par = (uint32_t)((s / NS) & 1);
        MBAR_WAIT(sb + slot * 16, par);

        const uint32_t abase  = sb + 1024 + (uint32_t)slot * GU_STAGE;
        const uint32_t bgbase = abase + 32768;
        const uint32_t bubase = abase + 40960;

#pragma unroll
        for (int ks = 0; ks < 4; ++ks) {
            uint32_t a[4][4];
#pragma unroll
            for (int mi = 0; mi < 4; ++mi) {
                uint32_t addr = abase + aro + (uint32_t)(mi * 16 * 128) +
                                (((uint32_t)(ks * 32) + acb) ^ xr);
                LDSM4(a[mi], addr);
            }
            uint32_t bg[2][2], bu[2][2];
            {
                uint32_t off = bro + (uint32_t)(ks * 16 * 128) + (bcb ^ xr);
                LDSM4T(bg[0][0], bg[0][1], bg[1][0], bg[1][1], bgbase + off);
                LDSM4T(bu[0][0], bu[0][1], bu[1][0], bu[1][1], bubase + off);
            }
#pragma unroll
            for (int mi = 0; mi < 4; ++mi)
#pragma unroll
                for (int nj = 0; nj < 2; ++nj) {
                    MMA16816(cg[mi][nj], a[mi], bg[nj]);
                    MMA16816(cu[mi][nj], a[mi], bu[nj]);
                }
        }

        if (lane == 0) MBAR_ARRIVE(sb + slot * 16 + 8);
        if (tid == 0 && s + NS < GU_KT) {
            MBAR_WAIT_RLX(sb + slot * 16 + 8, par);
            GU_LOAD(slot, s + NS);
        }
    }
#undef GU_LOAD

    // epilogue: h = silu(g) * u (warp-local)
#pragma unroll
    for (int mi = 0; mi < 4; ++mi)
#pragma unroll
        for (int nj = 0; nj < 2; ++nj) {
            int r = m0 + wm * 64 + mi * 16 + (lane >> 2);
            int c = n0 + wn * 16 + nj * 8 + (lane & 3) * 2;
            float g0 = cg[mi][nj][0], g1 = cg[mi][nj][1];
            float g2 = cg[mi][nj][2], g3 = cg[mi][nj][3];
            float u0 = cu[mi][nj][0], u1 = cu[mi][nj][1];
            float u2 = cu[mi][nj][2], u3 = cu[mi][nj][3];
            float h0 = g0 / (1.f + __expf(-g0)) * u0;
            float h1 = g1 / (1.f + __expf(-g1)) * u1;
            float h2 = g2 / (1.f + __expf(-g2)) * u2;
            float h3 = g3 / (1.f + __expf(-g3)) * u3;
            *(__half2*)(g_H + (size_t)r * II + c)       = __floats2half2_rn(h0, h1);
            *(__half2*)(g_H + (size_t)(r + 8) * II + c) = __floats2half2_rn(h2, h3);
        }
}

// ============================================================================
// GEMM2 (down): BM=256, BN=128, split-K=2 (z in {0,1}), 86 stages of BK=64.
// 512 threads = 16 warps = 4(m) x 4(n). Warp tile: 64 x 32. Same tiles as R4.
// z=0 -> out, z=1 -> g_P; reduce kernel adds. Grid 1024 CTAs -> 6.92 waves.
// ============================================================================
constexpr int DN_KT = II / 64 / 2;   // 86

__global__ __launch_bounds__(512, 1) void gemm_down(
    const __grid_constant__ CUtensorMap mA,
    const __grid_constant__ CUtensorMap mB,
    float* __restrict__ out)
{
    extern __shared__ __align__(1024) char smem[];
    const uint32_t sb = smem_u32(smem);
    const int tid  = threadIdx.x;
    const int lane = tid & 31;
    const int warp = tid >> 5;
    const int wm   = warp & 3;
    const int wn   = warp >> 2;
    const int m0   = blockIdx.x * 256;
    const int n0   = blockIdx.y * 128;
    const int kbase = blockIdx.z * DN_KT;          // stage offset for this split
    float* __restrict__ dst = blockIdx.z ? g_P : out;

    if (tid == 0) {
        for (int i = 0; i < NS; ++i) {
            MBAR_INIT(sb + i * 16, 1);
            MBAR_INIT(sb + i * 16 + 8, 16);
        }
    }
    __syncthreads();

#define DN_LOAD(slot, stg) do {                                     \
        uint32_t _d  = sb + 1024 + (uint32_t)(slot) * DN_STAGE;     \
        uint32_t _fb = sb + (slot) * 16;                            \
        int _k0 = (kbase + (stg)) * 64;                             \
        MBAR_EXPECT_TX(_fb, DN_STAGE);                              \
        TMA2D(_d,         &mA, _k0, m0,  _fb);                      \
        TMA2D(_d + 32768, &mB, n0,      _k0, _fb);                  \
        TMA2D(_d + 40960, &mB, n0 + 64, _k0, _fb);                  \
    } while (0)

    if (tid == 0) {
#pragma unroll
        for (int p = 0; p < NS; ++p) DN_LOAD(p, p);
    }

    float cc[4][4][4];
#pragma unroll
    for (int i = 0; i < 4; i++)
#pragma unroll
        for (int j = 0; j < 4; j++)
#pragma unroll
            for (int l = 0; l < 4; l++) cc[i][j][l] = 0.f;

    const uint32_t xr = (uint32_t)(lane & 7) << 4;
    const uint32_t aro = (uint32_t)(wm * 64 + (lane & 15)) * 128;
    const uint32_t acb = (uint32_t)((lane >> 4) << 4);
    const uint32_t bro = (uint32_t)(lane & 15) * 128;
    const uint32_t btile = (uint32_t)(wn >> 1) * 8192;     // which 64-col B tile
    const uint32_t bcb = (uint32_t)((wn & 1) * 64 + ((lane >> 4) << 4));

    for (int s = 0; s < DN_KT; ++s) {
        const int slot = s & (NS - 1);
        const uint32_t par = (uint32_t)((s / NS) & 1);
        MBAR_WAIT(sb + slot * 16, par);

        const uint32_t abase = sb + 1024 + (uint32_t)slot * DN_STAGE;
        const uint32_t bbase = abase + 32768 + btile;

#pragma unroll
        for (int ks = 0; ks < 4; ++ks) {
            uint32_t a[4][4];
#pragma unroll
            for (int mi = 0; mi < 4; ++mi) {
                uint32_t addr = abase + aro + (uint32_t)(mi * 16 * 128) +
                                (((uint32_t)(ks * 32) + acb) ^ xr);
                LDSM4(a[mi], addr);
            }
            uint32_t b[4][2];
#pragma unroll
            for (int nh = 0; nh < 2; ++nh) {
                uint32_t addr = bbase + bro + (uint32_t)(ks * 16 * 128) +
                                ((bcb + (uint32_t)(nh * 32)) ^ xr);
                LDSM4T(b[nh * 2][0], b[nh * 2][1], b[nh * 2 + 1][0], b[nh * 2 + 1][1], addr);
            }
#pragma unroll
            for (int mi = 0; mi < 4; ++mi)
#pragma unroll
                for (int nj = 0; nj < 4; ++nj) MMA16816(cc[mi][nj], a[mi], b[nj]);
        }

        if (lane == 0) MBAR_ARRIVE(sb + slot * 16 + 8);
        if (tid == 0 && s + NS < DN_KT) {
            MBAR_WAIT_RLX(sb + slot * 16 + 8, par);
            DN_LOAD(slot, s + NS);
        }
    }
#undef DN_LOAD

#pragma unroll
    for (int mi = 0; mi < 4; ++mi)
#pragma unroll
        for (int nj = 0; nj < 4; ++nj) {
            int r = m0 + wm * 64 + mi * 16 + (lane >> 2);
            int c = n0 + wn * 32 + nj * 8 + (lane & 3) * 2;
            *(float2*)(dst + (size_t)r * OO + c)       = make_float2(cc[mi][nj][0], cc[mi][nj][1]);
            *(float2*)(dst + (size_t)(r + 8) * OO + c) = make_float2(cc[mi][nj][2], cc[mi][nj][3]);
        }
}

// ---------------- split-K reduce: out += g_P ----------------
__global__ void reduce_kernel(float* __restrict__ out) {
    size_t i = (size_t)blockIdx.x * blockDim.x + threadIdx.x;  // one float4 each
    float4 a = ((const float4*)out)[i];
    float4 b = ((const float4*)g_P)[i];
    ((float4*)out)[i] = make_float4(a.x + b.x, a.y + b.y, a.z + b.z, a.w + b.w);
}

// ---------------- host: tensormap construction ----------------
typedef CUresult (*PFN_encode)(CUtensorMap*, CUtensorMapDataType, cuuint32_t, void*,
                               const cuuint64_t*, const cuuint64_t*, const cuuint32_t*,
                               const cuuint32_t*, CUtensorMapInterleave, CUtensorMapSwizzle,
                               CUtensorMapL2promotion, CUtensorMapFloatOOBfill);

static void make_map(PFN_encode enc, CUtensorMap* m, void* ptr,
                     unsigned long long d0, unsigned long long d1,
                     unsigned b0, unsigned b1) {
    cuuint64_t dims[2] = {d0, d1};
    cuuint64_t strides[1] = {d0 * 2};  // fp16 bytes
    cuuint32_t box[2] = {b0, b1};
    cuuint32_t es[2] = {1, 1};
    enc(m, CU_TENSOR_MAP_DATA_TYPE_FLOAT16, 2, ptr, dims, strides, box, es,
        CU_TENSOR_MAP_INTERLEAVE_NONE, CU_TENSOR_MAP_SWIZZLE_128B,
        CU_TENSOR_MAP_L2_PROMOTION_L2_128B, CU_TENSOR_MAP_FLOAT_OOB_FILL_NONE);
}

extern "C" void kernel_launch(void* const* d_in, const int* in_sizes, int n_in,
                              void* d_out, int out_size) {
    (void)in_sizes; (void)n_in; (void)out_size;
    const float* x   = (const float*)d_in[0];
    const int*   gqw = (const int*)d_in[1];
    const float* gsc = (const float*)d_in[2];
    const int*   gqz = (const int*)d_in[3];
    const int*   uqw = (const int*)d_in[4];
    const float* usc = (const float*)d_in[5];
    const int*   uqz = (const int*)d_in[6];
    const int*   dqw = (const int*)d_in[7];
    const float* dsc = (const float*)d_in[8];
    const int*   dqz = (const int*)d_in[9];
    float* out = (float*)d_out;

    PFN_encode enc = nullptr;
    cudaDriverEntryPointQueryResult qr;
    cudaGetDriverEntryPointByVersion("cuTensorMapEncodeTiled", (void**)&enc, 12000,
                                     cudaEnableDefault, &qr);
    void *pX, *pWg, *pWu, *pWd, *pH;
    cudaGetSymbolAddress(&pX,  g_X);
    cudaGetSymbolAddress(&pWg, g_Wg);
    cudaGetSymbolAddress(&pWu, g_Wu);
    cudaGetSymbolAddress(&pWd, g_Wd);
    cudaGetSymbolAddress(&pH,  g_H);

    static CUtensorMap mX, mWg, mWu, mWd, mH;
    make_map(enc, &mX,  pX,  KK, TT, 64, 256);  // A1: X [T,K]
    make_map(enc, &mWg, pWg, II, KK, 64, 64);   // Bg: Wg [K,I]
    make_map(enc, &mWu, pWu, II, KK, 64, 64);   // Bu
    make_map(enc, &mH,  pH,  II, TT, 64, 256);  // A2: H [T,I]
    make_map(enc, &mWd, pWd, OO, II, 64, 64);   // Bd: Wd [I,O]

    // x -> fp16
    f2h_kernel<<<(TT * KK / 4) / 256, 256>>>(x);

    // dequant weights
    int words1 = KK * (II / 8);
    dequant_kernel<0><<<(words1 + 255) / 256, 256>>>(gqw, gsc, gqz, KK, II);
    dequant_kernel<1><<<(words1 + 255) / 256, 256>>>(uqw, usc, uqz, KK, II);
    int words2 = II * (OO / 8);
    dequant_kernel<2><<<(words2 + 255) / 256, 256>>>(dqw, dsc, dqz, II, OO);

    // fused gate/up GEMM + silu*mul (TMA-fed)
    cudaFuncSetAttribute(gemm_gateup, cudaFuncAttributeMaxDynamicSharedMemorySize, SMEM_BYTES);
    gemm_gateup<<<dim3(TT / 256, II / 64), 512, SMEM_BYTES>>>(mX, mWg, mWu);

    // down GEMM (TMA-fed, split-K = 2)
    cudaFuncSetAttribute(gemm_down, cudaFuncAttributeMaxDynamicSharedMemorySize, SMEM_BYTES);
    gemm_down<<<dim3(TT / 256, OO / 128, 2), 512, SMEM_BYTES>>>(mH, mWd, out);

    // out += partial
    reduce_kernel<<<(TT * OO / 4) / 256, 256>>>(out);
}

// round 7
// speedup vs baseline: 1.0798x; 1.0236x over previous
#include <cuda_runtime.h>
#include <cuda_fp16.h>
#include <cuda.h>
#include <cstdint>

// Problem dims (fixed by the dataset)
constexpr int TT = 4096;    // tokens
constexpr int KK = 4096;    // in_features
constexpr int II = 11008;   // intermediate
constexpr int OO = 4096;    // out_features

constexpr int NS = 4;                    // pipeline stages
constexpr uint32_t GU_STAGE = 49152;     // A 32K | Bg 8K | Bu 8K
constexpr uint32_t DN_STAGE = 49152;     // A 32K | B0 8K | B1 8K
constexpr int SMEM_BYTES = 1024 + NS * 49152;  // 197632

// ---------------- device scratch ----------------
__device__ __align__(256) __half g_Wg[(size_t)KK * II];
__device__ __align__(256) __half g_Wu[(size_t)KK * II];
__device__ __align__(256) __half g_Wd[(size_t)II * OO];
__device__ __align__(256) __half g_X [(size_t)TT * KK];
__device__ __align__(256) __half g_H [(size_t)TT * II];
__device__ __align__(256) float  g_P [(size_t)TT * OO];   // split-K partial

// ---------------- PTX helpers ----------------
__device__ __forceinline__ uint32_t smem_u32(const void* p) {
    return (uint32_t)__cvta_generic_to_shared(p);
}

#define MBAR_INIT(addr, cnt) \
    asm volatile("mbarrier.init.shared.b64 [%0], %1;" :: "r"(addr), "r"(cnt) : "memory")

#define MBAR_EXPECT_TX(addr, bytes) \
    asm volatile("mbarrier.arrive.expect_tx.shared.b64 _, [%0], %1;" :: "r"(addr), "r"(bytes) : "memory")

#define MBAR_ARRIVE(addr) \
    asm volatile("mbarrier.arrive.shared.b64 _, [%0];" :: "r"(addr) : "memory")

#define MBAR_WAIT(addr, par) do {                                                       \
    uint32_t _m = (addr); uint32_t _p = (par); uint32_t _d;                             \
    asm volatile("{\n .reg .pred p;\n"                                                  \
        " mbarrier.try_wait.parity.acquire.cta.shared::cta.b64 p, [%1], %2;\n"          \
        " selp.b32 %0, 1, 0, p;\n}"                                                     \
        : "=r"(_d) : "r"(_m), "r"(_p) : "memory");                                      \
    if (!_d) {                                                                          \
        asm volatile("{\n .reg .pred P1;\n"                                             \
            "WL_%=:\n"                                                                  \
            " mbarrier.try_wait.parity.acquire.cta.shared::cta.b64 P1, [%0], %1, 0x989680;\n" \
            " @P1 bra.uni WD_%=;\n bra.uni WL_%=;\nWD_%=:\n}"                           \
            :: "r"(_m), "r"(_p) : "memory");                                            \
    }                                                                                   \
} while (0)

#define MBAR_WAIT_RLX(addr, par) do {                                                   \
    uint32_t _m = (addr); uint32_t _p = (par); uint32_t _d;                             \
    asm volatile("{\n .reg .pred p;\n"                                                  \
        " mbarrier.try_wait.parity.relaxed.cta.shared::cta.b64 p, [%1], %2, 0x989680;\n"\
        " selp.b32 %0, 1, 0, p;\n}"                                                     \
        : "=r"(_d) : "r"(_m), "r"(_p) : "memory");                                      \
    if (!_d) {                                                                          \
        asm volatile("{\n .reg .pred P1;\n"                                             \
            "WL_%=:\n"                                                                  \
            " mbarrier.try_wait.parity.relaxed.cta.shared::cta.b64 P1, [%0], %1, 0x989680;\n" \
            " @P1 bra.uni WD_%=;\n bra.uni WL_%=;\nWD_%=:\n}"                           \
            :: "r"(_m), "r"(_p) : "memory");                                            \
    }                                                                                   \
} while (0)

#define TMA2D(dst, map, c0, c1, bar) \
    asm volatile("cp.async.bulk.tensor.2d.shared::cta.global.tile.mbarrier::complete_tx::bytes " \
                 "[%0], [%1, {%2, %3}], [%4];" \
                 :: "r"(dst), "l"(map), "r"(c0), "r"(c1), "r"(bar) : "memory")

#define LDSM4(r, addr) \
    asm volatile("ldmatrix.sync.aligned.m8n8.x4.shared.b16 {%0,%1,%2,%3}, [%4];\n" \
        : "=r"((r)[0]), "=r"((r)[1]), "=r"((r)[2]), "=r"((r)[3]) : "r"(addr))

#define LDSM4T(r0, r1, r2, r3, addr) \
    asm volatile("ldmatrix.sync.aligned.m8n8.x4.trans.shared.b16 {%0,%1,%2,%3}, [%4];\n" \
        : "=r"(r0), "=r"(r1), "=r"(r2), "=r"(r3) : "r"(addr))

#define MMA16816(d, a, b) \
    asm volatile("mma.sync.aligned.m16n8k16.row.col.f32.f16.f16.f32 " \
        "{%0,%1,%2,%3}, {%4,%5,%6,%7}, {%8,%9}, {%0,%1,%2,%3};\n" \
        : "+f"((d)[0]), "+f"((d)[1]), "+f"((d)[2]), "+f"((d)[3]) \
        : "r"((a)[0]), "r"((a)[1]), "r"((a)[2]), "r"((a)[3]), "r"((b)[0]), "r"((b)[1]))

// ---------------- x fp32 -> fp16 ----------------
__global__ void f2h_kernel(const float* __restrict__ x) {
    size_t i = (size_t)blockIdx.x * blockDim.x + threadIdx.x;
    float4 v = ((const float4*)x)[i];
    __half2* o = (__half2*)g_X;
    o[2 * i + 0] = __floats2half2_rn(v.x, v.y);
    o[2 * i + 1] = __floats2half2_rn(v.z, v.w);
}

// ---------------- AWQ int4 dequant -> fp16 row-major [rows, cols] ----------------
// One thread owns one column-word (8 nibble columns) and 8 consecutive K rows
// (all inside one 128-row scale group): zero/scale setup hoisted out of the loop.
// Magic-number extraction: (w & 0xF) | 0x4B000000 viewed as float = 8388608 + n;
// subtracting (8388608 + z) is EXACT (integers < 2^24), then one f32 multiply —
// numerically identical to the old int path.
template <int WHICH>
__global__ void dequant_kernel(const int* __restrict__ qw, const float* __restrict__ sc,
                               const int* __restrict__ qz, int rows, int cols) {
    __half* W = (WHICH == 0) ? g_Wg : (WHICH == 1) ? g_Wu : g_Wd;
    const int wpr = cols >> 3;
    const int j = blockIdx.x * 256 + threadIdx.x;   // column word
    if (j >= wpr) return;
    const int k0 = blockIdx.y * 8;                   // 8 rows, same group
    const int grp = k0 >> 7;

    const unsigned z = ((const unsigned*)qz)[(size_t)grp * wpr + j];
    const float* srow = sc + (size_t)grp * cols + j * 8;
    const float4 s0 = *(const float4*)(srow);
    const float4 s1 = *(const float4*)(srow + 4);

    // per-byte constants: low nibble (mask 0x0F) and high nibble (mask 0xF0 = 16n)
    float blo[4], bhi[4], slo[4], shi[4];
#pragma unroll
    for (int p = 0; p < 4; ++p) {
        blo[p] = 8388608.0f + (float)((z >> (8 * p)) & 0xF);
        bhi[p] = 8388608.0f + 16.0f * (float)((z >> (8 * p + 4)) & 0xF);
    }
    slo[0] = s0.x; shi[0] = s0.y * 0.0625f;
    slo[1] = s0.z; shi[1] = s0.w * 0.0625f;
    slo[2] = s1.x; shi[2] = s1.y * 0.0625f;
    slo[3] = s1.z; shi[3] = s1.w * 0.0625f;

    const unsigned* qp = (const unsigned*)qw + (size_t)k0 * wpr + j;
    __half* wp = W + (size_t)k0 * cols + j * 8;

#pragma unroll
    for (int r = 0; r < 8; ++r) {
        const unsigned w = qp[(size_t)r * wpr];
        __half2 h[4];
#pragma unroll
        for (int p = 0; p < 4; ++p) {
            const unsigned t = w >> (8 * p);
            const float flo = (__uint_as_float((t & 0x0Fu) | 0x4B000000u) - blo[p]) * slo[p];
            const float fhi = (__uint_as_float((t & 0xF0u) | 0x4B000000u) - bhi[p]) * shi[p];
            h[p] = __floats2half2_rn(flo, fhi);
        }
        *(uint4*)(wp + (size_t)r * cols) = *(uint4*)h;
    }
}

// ============================================================================
// GEMM1 (fused gate+up): BM=256, 64 gate cols + 64 up cols, BK=64 per stage.
// 512 threads = 16 warps = 4(m) x 4(n). Warp: 64 rows x (16 gate + 16 up) cols.
// ============================================================================
constexpr int GU_KT = KK / 64;   // 64

__global__ __launch_bounds__(512, 1) void gemm_gateup(
    const __grid_constant__ CUtensorMap mA,
    const __grid_constant__ CUtensorMap mBg,
    const __grid_constant__ CUtensorMap mBu)
{
    extern __shared__ __align__(1024) char smem[];
    const uint32_t sb = smem_u32(smem);
    const int tid  = threadIdx.x;
    const int lane = tid & 31;
    const int warp = tid >> 5;
    const int wm   = warp & 3;
    const int wn   = warp >> 2;
    const int m0   = blockIdx.x * 256;
    const int n0   = blockIdx.y * 64;

    if (tid == 0) {
        for (int i = 0; i < NS; ++i) {
            MBAR_INIT(sb + i * 16, 1);       // full (tx-based)
            MBAR_INIT(sb + i * 16 + 8, 16);  // empty (one arrive per warp)
        }
    }
    __syncthreads();

#define GU_LOAD(slot, stg) do {                                     \
        uint32_t _d  = sb + 1024 + (uint32_t)(slot) * GU_STAGE;     \
        uint32_t _fb = sb + (slot) * 16;                            \
        int _k0 = (stg) * 64;                                       \
        MBAR_EXPECT_TX(_fb, GU_STAGE);                              \
        TMA2D(_d,         &mA,  _k0, m0, _fb);                      \
        TMA2D(_d + 32768, &mBg, n0,  _k0, _fb);                     \
        TMA2D(_d + 40960, &mBu, n0,  _k0, _fb);                     \
    } while (0)

    if (tid == 0) {
#pragma unroll
        for (int p = 0; p < NS; ++p) GU_LOAD(p, p);
    }

    float cg[4][2][4];
    float cu[4][2][4];
#pragma unroll
    for (int i = 0; i < 4; i++)
#pragma unroll
        for (int j = 0; j < 2; j++)
#pragma unroll
            for (int l = 0; l < 4; l++) { cg[i][j][l] = 0.f; cu[i][j][l] = 0.f; }

    const uint32_t xr = (uint32_t)(lane & 7) << 4;
    const uint32_t aro = (uint32_t)(wm * 64 + (lane & 15)) * 128;
    const uint32_t acb = (uint32_t)((lane >> 4) << 4);
    const uint32_t bro = (uint32_t)(lane & 15) * 128;
    const uint32_t bcb = (uint32_t)(wn * 32 + ((lane >> 4) << 4));

    for (int s = 0; s < GU_KT; ++s) {
        const int slot = s & (NS - 1);
        const uint32_t par = (uint32_t)((s / NS) & 1);
        MBAR_WAIT(sb + slot * 16, par);

        const uint32_t abase  = sb + 1024 + (uint32_t)slot * GU_STAGE;
        const uint32_t bgbase = abase + 32768;
        const uint32_t bubase = abase + 40960;

#pragma unroll
        for (int ks = 0; ks < 4; ++ks) {
            uint32_t a[4][4];
#pragma unroll
            for (int mi = 0; mi < 4; ++mi) {
                uint32_t addr = abase + aro + (uint32_t)(mi * 16 * 128) +
                                (((uint32_t)(ks * 32) + acb) ^ xr);
                LDSM4(a[mi], addr);
            }
            uint32_t bg[2][2], bu[2][2];
            {
                uint32_t off = bro + (uint32_t)(ks * 16 * 128) + (bcb ^ xr);
                LDSM4T(bg[0][0], bg[0][1], bg[1][0], bg[1][1], bgbase + off);
                LDSM4T(bu[0][0], bu[0][1], bu[1][0], bu[1][1], bubase + off);
            }
            // last smem reads for this stage issued -> release the buffer early
            if (ks == 3 && lane == 0) MBAR_ARRIVE(sb + slot * 16 + 8);
#pragma unroll
            for (int mi = 0; mi < 4; ++mi)
#pragma unroll
                for (int nj = 0; nj < 2; ++nj) {
                    MMA16816(cg[mi][nj], a[mi], bg[nj]);
                    MMA16816(cu[mi][nj], a[mi], bu[nj]);
                }
        }

        if (tid == 0 && s + NS < GU_KT) {
            MBAR_WAIT_RLX(sb + slot * 16 + 8, par);
            GU_LOAD(slot, s + NS);
        }
    }
#undef GU_LOAD

    // epilogue: h = silu(g) * u (warp-local)
#pragma unroll
    for (int mi = 0; mi < 4; ++mi)
#pragma unroll
        for (int nj = 0; nj < 2; ++nj) {
            int r = m0 + wm * 64 + mi * 16 + (lane >> 2);
            int c = n0 + wn * 16 + nj * 8 + (lane & 3) * 2;
            float g0 = cg[mi][nj][0], g1 = cg[mi][nj][1];
            float g2 = cg[mi][nj][2], g3 = cg[mi][nj][3];
            float u0 = cu[mi][nj][0], u1 = cu[mi][nj][1];
            float u2 = cu[mi][nj][2], u3 = cu[mi][nj][3];
            float h0 = g0 / (1.f + __expf(-g0)) * u0;
            float h1 = g1 / (1.f + __expf(-g1)) * u1;
            float h2 = g2 / (1.f + __expf(-g2)) * u2;
            float h3 = g3 / (1.f + __expf(-g3)) * u3;
            *(__half2*)(g_H + (size_t)r * II + c)       = __floats2half2_rn(h0, h1);
            *(__half2*)(g_H + (size_t)(r + 8) * II + c) = __floats2half2_rn(h2, h3);
        }
}

// ============================================================================
// GEMM2 (down): BM=256, BN=128, split-K=2 (z in {0,1}), 86 stages of BK=64.
// 512 threads = 16 warps = 4(m) x 4(n). Warp tile: 64 x 32.
// ============================================================================
constexpr int DN_KT = II / 64 / 2;   // 86

__global__ __launch_bounds__(512, 1) void gemm_down(
    const __grid_constant__ CUtensorMap mA,
    const __grid_constant__ CUtensorMap mB,
    float* __restrict__ out)
{
    extern __shared__ __align__(1024) char smem[];
    const uint32_t sb = smem_u32(smem);
    const int tid  = threadIdx.x;
    const int lane = tid & 31;
    const int warp = tid >> 5;
    const int wm   = warp & 3;
    const int wn   = warp >> 2;
    const int m0   = blockIdx.x * 256;
    const int n0   = blockIdx.y * 128;
    const int kbase = blockIdx.z * DN_KT;
    float* __restrict__ dst = blockIdx.z ? g_P : out;

    if (tid == 0) {
        for (int i = 0; i < NS; ++i) {
            MBAR_INIT(sb + i * 16, 1);
            MBAR_INIT(sb + i * 16 + 8, 16);
        }
    }
    __syncthreads();

#define DN_LOAD(slot, stg) do {                                     \
        uint32_t _d  = sb + 1024 + (uint32_t)(slot) * DN_STAGE;     \
        uint32_t _fb = sb + (slot) * 16;                            \
        int _k0 = (kbase + (stg)) * 64;                             \
        MBAR_EXPECT_TX(_fb, DN_STAGE);                              \
        TMA2D(_d,         &mA, _k0, m0,  _fb);                      \
        TMA2D(_d + 32768, &mB, n0,      _k0, _fb);                  \
        TMA2D(_d + 40960, &mB, n0 + 64, _k0, _fb);                  \
    } while (0)

    if (tid == 0) {
#pragma unroll
        for (int p = 0; p < NS; ++p) DN_LOAD(p, p);
    }

    float cc[4][4][4];
#pragma unroll
    for (int i = 0; i < 4; i++)
#pragma unroll
        for (int j = 0; j < 4; j++)
#pragma unroll
            for (int l = 0; l < 4; l++) cc[i][j][l] = 0.f;

    const uint32_t xr = (uint32_t)(lane & 7) << 4;
    const uint32_t aro = (uint32_t)(wm * 64 + (lane & 15)) * 128;
    const uint32_t acb = (uint32_t)((lane >> 4) << 4);
    const uint32_t bro = (uint32_t)(lane & 15) * 128;
    const uint32_t btile = (uint32_t)(wn >> 1) * 8192;
    const uint32_t bcb = (uint32_t)((wn & 1) * 64 + ((lane >> 4) << 4));

    for (int s = 0; s < DN_KT; ++s) {
        const int slot = s & (NS - 1);
        const uint32_t par = (uint32_t)((s / NS) & 1);
        MBAR_WAIT(sb + slot * 16, par);

        const uint32_t abase = sb + 1024 + (uint32_t)slot * DN_STAGE;
        const uint32_t bbase = abase + 32768 + btile;

#pragma unroll
        for (int ks = 0; ks < 4; ++ks) {
            uint32_t a[4][4];
#pragma unroll
            for (int mi = 0; mi < 4; ++mi) {
                uint32_t addr = abase + aro + (uint32_t)(mi * 16 * 128) +
                                (((uint32_t)(ks * 32) + acb) ^ xr);
                LDSM4(a[mi], addr);
            }
            uint32_t b[4][2];
#pragma unroll
            for (int nh = 0; nh < 2; ++nh) {
                uint32_t addr = bbase + bro + (uint32_t)(ks * 16 * 128) +
                                ((bcb + (uint32_t)(nh * 32)) ^ xr);
                LDSM4T(b[nh * 2][0], b[nh * 2][1], b[nh * 2 + 1][0], b[nh * 2 + 1][1], addr);
            }
            if (ks == 3 && lane == 0) MBAR_ARRIVE(sb + slot * 16 + 8);
#pragma unroll
            for (int mi = 0; mi < 4; ++mi)
#pragma unroll
                for (int nj = 0; nj < 4; ++nj) MMA16816(cc[mi][nj], a[mi], b[nj]);
        }

        if (tid == 0 && s + NS < DN_KT) {
            MBAR_WAIT_RLX(sb + slot * 16 + 8, par);
            DN_LOAD(slot, s + NS);
        }
    }
#undef DN_LOAD

#pragma unroll
    for (int mi = 0; mi < 4; ++mi)
#pragma unroll
        for (int nj = 0; nj < 4; ++nj) {
            int r = m0 + wm * 64 + mi * 16 + (lane >> 2);
            int c = n0 + wn * 32 + nj * 8 + (lane & 3) * 2;
            *(float2*)(dst + (size_t)r * OO + c)       = make_float2(cc[mi][nj][0], cc[mi][nj][1]);
            *(float2*)(dst + (size_t)(r + 8) * OO + c) = make_float2(cc[mi][nj][2], cc[mi][nj][3]);
        }
}

// ---------------- split-K reduce: out += g_P ----------------
__global__ void reduce_kernel(float* __restrict__ out) {
    size_t i = (size_t)blockIdx.x * blockDim.x + threadIdx.x;
    float4 a = ((const float4*)out)[i];
    float4 b = ((const float4*)g_P)[i];
    ((float4*)out)[i] = make_float4(a.x + b.x, a.y + b.y, a.z + b.z, a.w + b.w);
}

// ---------------- host: tensormap construction ----------------
typedef CUresult (*PFN_encode)(CUtensorMap*, CUtensorMapDataType, cuuint32_t, void*,
                               const cuuint64_t*, const cuuint64_t*, const cuuint32_t*,
                               const cuuint32_t*, CUtensorMapInterleave, CUtensorMapSwizzle,
                               CUtensorMapL2promotion, CUtensorMapFloatOOBfill);

static void make_map(PFN_encode enc, CUtensorMap* m, void* ptr,
                     unsigned long long d0, unsigned long long d1,
                     unsigned b0, unsigned b1) {
    cuuint64_t dims[2] = {d0, d1};
    cuuint64_t strides[1] = {d0 * 2};  // fp16 bytes
    cuuint32_t box[2] = {b0, b1};
    cuuint32_t es[2] = {1, 1};
    enc(m, CU_TENSOR_MAP_DATA_TYPE_FLOAT16, 2, ptr, dims, strides, box, es,
        CU_TENSOR_MAP_INTERLEAVE_NONE, CU_TENSOR_MAP_SWIZZLE_128B,
        CU_TENSOR_MAP_L2_PROMOTION_L2_128B, CU_TENSOR_MAP_FLOAT_OOB_FILL_NONE);
}

extern "C" void kernel_launch(void* const* d_in, const int* in_sizes, int n_in,
                              void* d_out, int out_size) {
    (void)in_sizes; (void)n_in; (void)out_size;
    const float* x   = (const float*)d_in[0];
    const int*   gqw = (const int*)d_in[1];
    const float* gsc = (const float*)d_in[2];
    const int*   gqz = (const int*)d_in[3];
    const int*   uqw = (const int*)d_in[4];
    const float* usc = (const float*)d_in[5];
    const int*   uqz = (const int*)d_in[6];
    const int*   dqw = (const int*)d_in[7];
    const float* dsc = (const float*)d_in[8];
    const int*   dqz = (const int*)d_in[9];
    float* out = (float*)d_out;

    PFN_encode enc = nullptr;
    cudaDriverEntryPointQueryResult qr;
    cudaGetDriverEntryPointByVersion("cuTensorMapEncodeTiled", (void**)&enc, 12000,
                                     cudaEnableDefault, &qr);
    void *pX, *pWg, *pWu, *pWd, *pH;
    cudaGetSymbolAddress(&pX,  g_X);
    cudaGetSymbolAddress(&pWg, g_Wg);
    cudaGetSymbolAddress(&pWu, g_Wu);
    cudaGetSymbolAddress(&pWd, g_Wd);
    cudaGetSymbolAddress(&pH,  g_H);

    static CUtensorMap mX, mWg, mWu, mWd, mH;
    make_map(enc, &mX,  pX,  KK, TT, 64, 256);  // A1: X [T,K]
    make_map(enc, &mWg, pWg, II, KK, 64, 64);   // Bg: Wg [K,I]
    make_map(enc, &mWu, pWu, II, KK, 64, 64);   // Bu
    make_map(enc, &mH,  pH,  II, TT, 64, 256);  // A2: H [T,I]
    make_map(enc, &mWd, pWd, OO, II, 64, 64);   // Bd: Wd [I,O]

    // x -> fp16
    f2h_kernel<<<(TT * KK / 4) / 256, 256>>>(x);

    // dequant weights (2D grid: x = column words, y = 8-row octets)
    {
        int wpr1 = II / 8;   // 1376
        dim3 g1((wpr1 + 255) / 256, KK / 8);
        dequant_kernel<0><<<g1, 256>>>(gqw, gsc, gqz, KK, II);
        dequant_kernel<1><<<g1, 256>>>(uqw, usc, uqz, KK, II);
        int wpr2 = OO / 8;   // 512
        dim3 g2((wpr2 + 255) / 256, II / 8);
        dequant_kernel<2><<<g2, 256>>>(dqw, dsc, dqz, II, OO);
    }

    // fused gate/up GEMM + silu*mul (TMA-fed)
    cudaFuncSetAttribute(gemm_gateup, cudaFuncAttributeMaxDynamicSharedMemorySize, SMEM_BYTES);
    gemm_gateup<<<dim3(TT / 256, II / 64), 512, SMEM_BYTES>>>(mX, mWg, mWu);

    // down GEMM (TMA-fed, split-K = 2)
    cudaFuncSetAttribute(gemm_down, cudaFuncAttributeMaxDynamicSharedMemorySize, SMEM_BYTES);
    gemm_down<<<dim3(TT / 256, OO / 128, 2), 512, SMEM_BYTES>>>(mH, mWd, out);

    // out += partial
    reduce_kernel<<<(TT * OO / 4) / 256, 256>>>(out);
}